// round 3
// baseline (speedup 1.0000x reference)
#include <cuda_runtime.h>
#include <math.h>

// ---------------------------------------------------------------------------
// VQ-VAE forward, fp32. Round 3: packed fma.rn.f32x2 inner loops, occupancy
// fix for res 3x3 (TCO=2), fused stats kernel.
// Output layout: [loss, x_recon(1572864), perplexity]
// ---------------------------------------------------------------------------

typedef unsigned long long u64;

__device__ __forceinline__ u64 pk(float lo, float hi) {
    u64 r;
    asm("mov.b64 %0, {%1, %2};" : "=l"(r) : "f"(lo), "f"(hi));
    return r;
}
__device__ __forceinline__ void fma2(u64& d, u64 a, u64 b) {
    asm("fma.rn.f32x2 %0, %1, %2, %0;" : "+l"(d) : "l"(a), "l"(b));
}
__device__ __forceinline__ float2 upk(u64 v) {
    float lo, hi;
    asm("mov.b64 {%0, %1}, %2;" : "=f"(lo), "=f"(hi) : "l"(v));
    return make_float2(lo, hi);
}

// Scratch (device globals; no allocation allowed)
__device__ float g_A[32u * 64 * 64 * 64];
__device__ float g_B[32u * 128 * 32 * 32];
__device__ float g_C[32u * 128 * 32 * 32];
__device__ float g_T[32u * 32 * 32 * 32];
__device__ float g_Z[32u * 64 * 32 * 32];
__device__ float g_Q[32u * 64 * 32 * 32];
__device__ float g_G[32u * 128 * 32 * 32];
__device__ int   g_idx[32768];
__device__ float g_cnorm[512];
__device__ float g_err[32768];

// ---------------------------------------------------------------------------
// Direct conv, templated, packed f32x2 accumulation. TX=8 outputs along x
// (4 packed pairs), TCO output channels per thread.
// ---------------------------------------------------------------------------
template <int KH, int KW, int S, int P, int TCO,
          int CIN, int HIN, int WIN, int COUT, int HOUT, int WOUT,
          bool IN_RELU, bool OUT_RELU, bool BIAS, bool ADD>
__global__ __launch_bounds__(128)
void conv_k(const float* __restrict__ in, const float* __restrict__ wt,
            const float* __restrict__ bs, float* __restrict__ out,
            const float* __restrict__ res)
{
    constexpr int TX   = 8;
    constexpr int WINW = (TX - 1) * S + KW;
    static_assert((HOUT * WOUT / TX) % 128 == 0, "tile count must fill blocks");

    int tid = blockIdx.x * 128 + threadIdx.x;
    int ox0 = (tid * TX) % WOUT;
    int oy  = (tid * TX) / WOUT;
    int co0 = blockIdx.y * TCO;
    int b   = blockIdx.z;

    u64 acc[TCO][4];
#pragma unroll
    for (int c = 0; c < TCO; c++) {
        float bv = BIAS ? __ldg(bs + co0 + c) : 0.f;
        u64 bp = pk(bv, bv);
#pragma unroll
        for (int p = 0; p < 4; p++) acc[c][p] = bp;
    }

    const float* inb = in + (size_t)b * CIN * HIN * WIN;
    const int ixb = ox0 * S - P;

#pragma unroll 1
    for (int ci = 0; ci < CIN; ci++) {
        const float* ip  = inb + ci * HIN * WIN;
        const float* wci = wt + ((size_t)co0 * CIN + ci) * KH * KW;
#pragma unroll
        for (int ky = 0; ky < KH; ky++) {
            int iy = oy * S - P + ky;
            if (P > 0 && (iy < 0 || iy >= HIN)) continue;
            const float* row = ip + iy * WIN;
            float w[WINW];
            if constexpr (P == 0) {
                float4 v0 = *(const float4*)(row + ox0);
                float4 v1 = *(const float4*)(row + ox0 + 4);
                w[0] = v0.x; w[1] = v0.y; w[2] = v0.z; w[3] = v0.w;
                w[4] = v1.x; w[5] = v1.y; w[6] = v1.z; w[7] = v1.w;
            } else {
                w[0] = (ixb >= 0) ? row[ixb] : 0.f;
#pragma unroll
                for (int m = 0; m < (WINW - 2) / 4; m++) {
                    float4 v = *(const float4*)(row + ixb + 1 + 4 * m);
                    w[1 + 4 * m] = v.x; w[2 + 4 * m] = v.y;
                    w[3 + 4 * m] = v.z; w[4 + 4 * m] = v.w;
                }
                w[WINW - 1] = (ixb + WINW - 1 < WIN) ? row[ixb + WINW - 1] : 0.f;
            }
            if (IN_RELU) {
#pragma unroll
                for (int m = 0; m < WINW; m++) w[m] = fmaxf(w[m], 0.f);
            }

            if constexpr (KW == 3 && S == 1) {
                // pairs: e[m]=(w2m,w2m+1) m0..4 ; o[m]=(w2m+1,w2m+2) m0..3
                u64 e[5], o[4];
#pragma unroll
                for (int m = 0; m < 5; m++) e[m] = pk(w[2 * m], w[2 * m + 1]);
#pragma unroll
                for (int m = 0; m < 4; m++) o[m] = pk(w[2 * m + 1], w[2 * m + 2]);
#pragma unroll
                for (int c = 0; c < TCO; c++) {
                    const float* wp = wci + c * CIN * 9 + ky * 3;
                    u64 W0 = pk(__ldg(wp),     __ldg(wp));
                    u64 W1 = pk(__ldg(wp + 1), __ldg(wp + 1));
                    u64 W2 = pk(__ldg(wp + 2), __ldg(wp + 2));
#pragma unroll
                    for (int p = 0; p < 4; p++) {
                        fma2(acc[c][p], e[p],     W0);
                        fma2(acc[c][p], o[p],     W1);
                        fma2(acc[c][p], e[p + 1], W2);
                    }
                }
            } else if constexpr (KW == 1) {
                u64 e[4];
#pragma unroll
                for (int m = 0; m < 4; m++) e[m] = pk(w[2 * m], w[2 * m + 1]);
#pragma unroll
                for (int c = 0; c < TCO; c++) {
                    float wv = __ldg(wci + c * CIN);
                    u64 W = pk(wv, wv);
#pragma unroll
                    for (int p = 0; p < 4; p++) fma2(acc[c][p], e[p], W);
                }
            } else {   // KW==4, S==2
                // pair p covers outputs (2p,2p+1); lanes w[kx+4p], w[kx+4p+2]
                float4 wv[TCO];
#pragma unroll
                for (int c = 0; c < TCO; c++)
                    wv[c] = *(const float4*)(wci + c * CIN * 16 + ky * 4);
#pragma unroll
                for (int kx = 0; kx < 4; kx++) {
                    u64 pr[4];
#pragma unroll
                    for (int p = 0; p < 4; p++)
                        pr[p] = pk(w[kx + 4 * p], w[kx + 4 * p + 2]);
#pragma unroll
                    for (int c = 0; c < TCO; c++) {
                        float wk = (kx == 0) ? wv[c].x : (kx == 1) ? wv[c].y
                                 : (kx == 2) ? wv[c].z : wv[c].w;
                        u64 W = pk(wk, wk);
#pragma unroll
                        for (int p = 0; p < 4; p++) fma2(acc[c][p], pr[p], W);
                    }
                }
            }
        }
    }

#pragma unroll
    for (int c = 0; c < TCO; c++) {
        size_t o = (((size_t)b * COUT + (co0 + c)) * HOUT + oy) * WOUT + ox0;
        float v[TX];
#pragma unroll
        for (int p = 0; p < 4; p++) {
            float2 f = upk(acc[c][p]);
            v[2 * p] = f.x; v[2 * p + 1] = f.y;
        }
        if (ADD) {
            float4 r0 = *(const float4*)(res + o);
            float4 r1 = *(const float4*)(res + o + 4);
            v[0] += r0.x; v[1] += r0.y; v[2] += r0.z; v[3] += r0.w;
            v[4] += r1.x; v[5] += r1.y; v[6] += r1.z; v[7] += r1.w;
        }
        if (OUT_RELU) {
#pragma unroll
            for (int j = 0; j < TX; j++) v[j] = fmaxf(v[j], 0.f);
        }
        *(float4*)(out + o)     = make_float4(v[0], v[1], v[2], v[3]);
        *(float4*)(out + o + 4) = make_float4(v[4], v[5], v[6], v[7]);
    }
}

// ---------------------------------------------------------------------------
// ConvTranspose2d(k=4,s=2,p=1) direct gather, packed f32x2.
// ---------------------------------------------------------------------------
template <int TCO, int CIN, int HIN, int WIN, int COUT, int HOUT, int WOUT,
          bool IN_RELU, bool OUT_RELU, bool VEC_ST>
__global__ __launch_bounds__(128)
void deconv_k(const float* __restrict__ in, const float* __restrict__ wt,
              const float* __restrict__ bs, float* __restrict__ out)
{
    constexpr int TX = 8;
    static_assert((HOUT * WOUT / TX) % 128 == 0, "tile count must fill blocks");

    int tid = blockIdx.x * 128 + threadIdx.x;
    int ox0 = (tid * TX) % WOUT;
    int oy  = (tid * TX) / WOUT;
    int co0 = blockIdx.y * TCO;
    int b   = blockIdx.z;

    u64 acc[TCO][4];
#pragma unroll
    for (int c = 0; c < TCO; c++) {
        float bv = __ldg(bs + co0 + c);
        u64 bp = pk(bv, bv);
#pragma unroll
        for (int p = 0; p < 4; p++) acc[c][p] = bp;
    }

    const int ixb = ox0 / 2 - 1;
    const int oyp = oy & 1;
    const float* inb = in + (size_t)b * CIN * HIN * WIN;

#pragma unroll 1
    for (int ci = 0; ci < CIN; ci++) {
        const float* ip  = inb + ci * HIN * WIN;
        const float* wci = wt + ((size_t)co0 * CIN + ci) * 16;
#pragma unroll
        for (int t = 0; t < 2; t++) {
            int ky = oyp + 2 * t;
            int iy = (oy - 2 + ky) >> 1;
            if (iy < 0 || iy >= HIN) continue;
            const float* row = ip + iy * WIN;
            float u[6];
            u[0] = (ixb >= 0) ? row[ixb] : 0.f;
            float4 v = *(const float4*)(row + ixb + 1);
            u[1] = v.x; u[2] = v.y; u[3] = v.z; u[4] = v.w;
            u[5] = (ixb + 5 < WIN) ? row[ixb + 5] : 0.f;
            if (IN_RELU) {
#pragma unroll
                for (int m = 0; m < 6; m++) u[m] = fmaxf(u[m], 0.f);
            }
            u64 a[5];
#pragma unroll
            for (int m = 0; m < 5; m++) a[m] = pk(u[m], u[m + 1]);
#pragma unroll
            for (int c = 0; c < TCO; c++) {
                float4 wv = *(const float4*)(wci + c * CIN * 16 + ky * 4);
                u64 wlo = pk(wv.x, wv.y);
                u64 whi = pk(wv.z, wv.w);
                // pair p -> outputs (2p, 2p+1):
                //   lane0: u[p]*wv.x + u[p+1]*wv.z ; lane1: u[p+1]*wv.y + u[p+2]*wv.w
#pragma unroll
                for (int p = 0; p < 4; p++) {
                    fma2(acc[c][p], a[p],     wlo);
                    fma2(acc[c][p], a[p + 1], whi);
                }
            }
        }
    }

#pragma unroll
    for (int c = 0; c < TCO; c++) {
        size_t o = (((size_t)b * COUT + (co0 + c)) * HOUT + oy) * WOUT + ox0;
        float v[TX];
#pragma unroll
        for (int p = 0; p < 4; p++) {
            float2 f = upk(acc[c][p]);
            v[2 * p] = f.x; v[2 * p + 1] = f.y;
        }
        if (OUT_RELU) {
#pragma unroll
            for (int j = 0; j < TX; j++) v[j] = fmaxf(v[j], 0.f);
        }
        if constexpr (VEC_ST) {
            *(float4*)(out + o)     = make_float4(v[0], v[1], v[2], v[3]);
            *(float4*)(out + o + 4) = make_float4(v[4], v[5], v[6], v[7]);
        } else {
#pragma unroll
            for (int j = 0; j < TX; j++) out[o + j] = v[j];
        }
    }
}

// ---------------------------------------------------------------------------
// VQ
// ---------------------------------------------------------------------------
__global__ void cnorm_kernel(const float* __restrict__ cb, float* __restrict__ cn)
{
    int k = blockIdx.x * blockDim.x + threadIdx.x;
    if (k >= 512) return;
    const float* c = cb + k * 64;
    float s = 0.f;
#pragma unroll
    for (int d = 0; d < 64; d++) s = fmaf(c[d], c[d], s);
    cn[k] = s;
}

__global__ __launch_bounds__(256)
void vq_kernel(const float* __restrict__ z, const float* __restrict__ cb,
               const float* __restrict__ cn, int* __restrict__ idx,
               float* __restrict__ q, float* __restrict__ err)
{
    int p = blockIdx.x * blockDim.x + threadIdx.x;  // 0..32767
    if (p >= 32768) return;
    int b = p >> 10, s = p & 1023;
    const float* zp = z + (size_t)b * 64 * 1024 + s;
    float zv[64];
#pragma unroll
    for (int d = 0; d < 64; d++) zv[d] = zp[d * 1024];
    u64 z2[32];
#pragma unroll
    for (int m = 0; m < 32; m++) z2[m] = pk(zv[2 * m], zv[2 * m + 1]);

    float best = 3.4e38f;
    int bk = 0;
#pragma unroll 1
    for (int k = 0; k < 512; k++) {
        // codebook rows are 16B-aligned; ulonglong2 lanes = packed f32 pairs
        const ulonglong2* c2 = (const ulonglong2*)(cb + (size_t)k * 64);
        u64 s0 = 0, s1 = 0;   // f32x2 accumulators (0,0)
#pragma unroll
        for (int m = 0; m < 16; m++) {
            ulonglong2 cv = __ldg(c2 + m);
            fma2(s0, z2[2 * m],     cv.x);
            fma2(s1, z2[2 * m + 1], cv.y);
        }
        float2 f0 = upk(s0), f1 = upk(s1);
        float dist = __ldg(cn + k) - 2.f * ((f0.x + f0.y) + (f1.x + f1.y));
        if (dist < best) { best = dist; bk = k; }   // strict <: first-min (jnp.argmin)
    }
    idx[p] = bk;
    float* qp = q + (size_t)b * 64 * 1024 + s;
    const float* c = cb + (size_t)bk * 64;
    float e = 0.f;
#pragma unroll
    for (int d = 0; d < 64; d++) {
        float cd = __ldg(c + d);
        qp[d * 1024] = cd;
        float df = zv[d] - cd;
        e = fmaf(df, df, e);
    }
    err[p] = e;
}

// hist + loss + perplexity in one block
__global__ __launch_bounds__(512)
void stats_kernel(const int* __restrict__ idx, const float* __restrict__ err,
                  float* __restrict__ out0, float* __restrict__ outp)
{
    __shared__ int   h[512];
    __shared__ float sm[512];
    int t = threadIdx.x;
    h[t] = 0;
    float s = 0.f;
    __syncthreads();
    for (int i = t; i < 32768; i += 512) {
        atomicAdd(&h[idx[i]], 1);
        s += err[i];
    }
    sm[t] = s;
    __syncthreads();
    for (int off = 256; off > 0; off >>= 1) {
        if (t < off) sm[t] += sm[t + off];
        __syncthreads();
    }
    if (t == 0) out0[0] = 1.25f * sm[0] / 2097152.0f;   // (1+beta)*mse
    __syncthreads();
    float pr = (float)h[t] * (1.0f / 32768.0f);
    sm[t] = pr * logf(pr + 1e-10f);
    __syncthreads();
    for (int off = 256; off > 0; off >>= 1) {
        if (t < off) sm[t] += sm[t + off];
        __syncthreads();
    }
    if (t == 0) outp[0] = expf(-sm[0]);
}

// ---------------------------------------------------------------------------
// Launch
// ---------------------------------------------------------------------------
extern "C" void kernel_launch(void* const* d_in, const int* in_sizes, int n_in,
                              void* d_out, int out_size)
{
    const float* x     = (const float*)d_in[0];
    const float* e_w1  = (const float*)d_in[1];
    const float* e_b1  = (const float*)d_in[2];
    const float* e_w2  = (const float*)d_in[3];
    const float* e_b2  = (const float*)d_in[4];
    const float* e_w3  = (const float*)d_in[5];
    const float* e_b3  = (const float*)d_in[6];
    const float* e_r1a = (const float*)d_in[7];
    const float* e_r1b = (const float*)d_in[8];
    const float* e_r2a = (const float*)d_in[9];
    const float* e_r2b = (const float*)d_in[10];
    const float* pre_w = (const float*)d_in[11];
    const float* pre_b = (const float*)d_in[12];
    const float* cb    = (const float*)d_in[13];
    const float* d_w1  = (const float*)d_in[14];
    const float* d_b1  = (const float*)d_in[15];
    const float* d_r1a = (const float*)d_in[16];
    const float* d_r1b = (const float*)d_in[17];
    const float* d_r2a = (const float*)d_in[18];
    const float* d_r2b = (const float*)d_in[19];
    const float* dt_w1 = (const float*)d_in[20];
    const float* dt_b1 = (const float*)d_in[21];
    const float* dt_w2 = (const float*)d_in[22];
    const float* dt_b2 = (const float*)d_in[23];
    float* out = (float*)d_out;

    float *A, *Bf, *Cc, *T, *Z, *Q, *G, *cn, *err;
    int *idx;
    cudaGetSymbolAddress((void**)&A,    g_A);
    cudaGetSymbolAddress((void**)&Bf,   g_B);
    cudaGetSymbolAddress((void**)&Cc,   g_C);
    cudaGetSymbolAddress((void**)&T,    g_T);
    cudaGetSymbolAddress((void**)&Z,    g_Z);
    cudaGetSymbolAddress((void**)&Q,    g_Q);
    cudaGetSymbolAddress((void**)&G,    g_G);
    cudaGetSymbolAddress((void**)&cn,   g_cnorm);
    cudaGetSymbolAddress((void**)&err,  g_err);
    cudaGetSymbolAddress((void**)&idx,  g_idx);

    dim3 blk(128);

    // ---- encoder ----
    conv_k<4,4,2,1,4, 3,128,128, 64,64,64, false,true,true,false>
        <<<dim3(4, 16, 32), blk>>>(x, e_w1, e_b1, A, nullptr);
    conv_k<4,4,2,1,4, 64,64,64, 128,32,32, false,true,true,false>
        <<<dim3(1, 32, 32), blk>>>(A, e_w2, e_b2, Bf, nullptr);
    conv_k<3,3,1,1,4, 128,32,32, 128,32,32, false,false,true,false>
        <<<dim3(1, 32, 32), blk>>>(Bf, e_w3, e_b3, Cc, nullptr);
    for (int rb = 0; rb < 2; rb++) {
        const float* wa = (rb == 0) ? e_r1a : e_r2a;
        const float* wb = (rb == 0) ? e_r1b : e_r2b;
        conv_k<3,3,1,1,2, 128,32,32, 32,32,32, true,false,false,false>
            <<<dim3(1, 16, 32), blk>>>(Cc, wa, nullptr, T, nullptr);
        conv_k<1,1,1,0,4, 32,32,32, 128,32,32, true,false,false,true>
            <<<dim3(1, 32, 32), blk>>>(T, wb, nullptr, Cc, Cc);
    }
    conv_k<1,1,1,0,4, 128,32,32, 64,32,32, true,false,true,false>
        <<<dim3(1, 16, 32), blk>>>(Cc, pre_w, pre_b, Z, nullptr);

    // ---- vector quantizer ----
    cnorm_kernel<<<2, 256>>>(cb, cn);
    vq_kernel<<<128, 256>>>(Z, cb, cn, idx, Q, err);
    stats_kernel<<<1, 512>>>(idx, err, out, out + (out_size - 1));

    // ---- decoder ----
    conv_k<3,3,1,1,4, 64,32,32, 128,32,32, false,false,true,false>
        <<<dim3(1, 32, 32), blk>>>(Q, d_w1, d_b1, G, nullptr);
    for (int rb = 0; rb < 2; rb++) {
        const float* wa = (rb == 0) ? d_r1a : d_r2a;
        const float* wb = (rb == 0) ? d_r1b : d_r2b;
        conv_k<3,3,1,1,2, 128,32,32, 32,32,32, true,false,false,false>
            <<<dim3(1, 16, 32), blk>>>(G, wa, nullptr, T, nullptr);
        conv_k<1,1,1,0,4, 32,32,32, 128,32,32, true,false,false,true>
            <<<dim3(1, 32, 32), blk>>>(T, wb, nullptr, G, G);
    }
    deconv_k<4, 128,32,32, 64,64,64, true,true,true>
        <<<dim3(4, 16, 32), blk>>>(G, dt_w1, dt_b1, A);
    deconv_k<3, 64,64,64, 3,128,128, false,false,false>
        <<<dim3(16, 1, 32), blk>>>(A, dt_w2, dt_b2, out + 1);
}